// round 11
// baseline (speedup 1.0000x reference)
#include <cuda_runtime.h>
#include <cuda_fp16.h>
#include <cstdint>

// Problem constants
#define DMODEL 512
#define FFN    2048
#define NEXP   8
#define TOPK   2
#define NTOK   8192
#define NROWS  (NTOK * TOPK)
#define TILE   128
#define BK     64          // fp16 K elems per smem chunk
#define PAD    72          // smem row stride in fp16 (144 B)

#define ABYTES (TILE * PAD * 2)      // 18432 B (128-row array)
#define STAGE  (2 * ABYTES)          // gemm1 stage = 36864 B
#define NSTG   3
#define DSMEM1 (NSTG * STAGE)        // 110592 B

// gemm2: TILE_M=64, TILE_N=128
#define A2BYTES (64 * PAD * 2)       // 9216 B
#define STAGE2  (A2BYTES + ABYTES)   // 27648 B
#define DSMEM2  (NSTG * STAGE2)      // 82944 B

// ---------------------------------------------------------------------------
// Device scratch (static).
// ---------------------------------------------------------------------------
__device__ __half g_xh[(size_t)NTOK * DMODEL];
__device__ __half g_w1h[(size_t)NEXP * FFN * DMODEL];   // [E][F][D] transposed, fp16
__device__ __half g_w2h[(size_t)NEXP * DMODEL * FFN];   // [E][D][F] transposed, fp16
__device__ __half g_hh[(size_t)NROWS * FFN];
__device__ int   g_cnt[NEXP];
__device__ int   g_off[NEXP];
__device__ int   g_cursor[NEXP];
__device__ int   g_tok[NROWS];
__device__ float g_gate[NROWS];
__device__ int   g_pick_e[NROWS];
__device__ float g_pick_w[NROWS];

// ---------------------------------------------------------------------------
__device__ __forceinline__ uint32_t smem_u32(const void* p) {
    uint32_t a;
    asm("{ .reg .u64 t; cvta.to.shared.u64 t, %1; cvt.u32.u64 %0, t; }" : "=r"(a) : "l"(p));
    return a;
}

#define LDSM4(R0, R1, R2, R3, ADDR) \
    asm volatile("ldmatrix.sync.aligned.m8n8.x4.shared.b16 {%0,%1,%2,%3}, [%4];" \
                 : "=r"(R0), "=r"(R1), "=r"(R2), "=r"(R3) : "r"(ADDR))

#define MMA16816(C, A, B0, B1) \
    asm volatile("mma.sync.aligned.m16n8k16.row.col.f32.f16.f16.f32 " \
                 "{%0,%1,%2,%3}, {%4,%5,%6,%7}, {%8,%9}, {%0,%1,%2,%3};" \
                 : "+f"((C)[0]), "+f"((C)[1]), "+f"((C)[2]), "+f"((C)[3]) \
                 : "r"((A)[0]), "r"((A)[1]), "r"((A)[2]), "r"((A)[3]), "r"(B0), "r"(B1))

#define CPA16(DST, SRC) \
    asm volatile("cp.async.cg.shared.global [%0], [%1], 16;" :: "r"(DST), "l"(SRC))
#define CP_COMMIT() asm volatile("cp.async.commit_group;")
#define CP_WAIT2()  asm volatile("cp.async.wait_group 2;")

// ---------------------------------------------------------------------------
__global__ void zero_kernel(float* __restrict__ out, int n) {
    int i = blockIdx.x * blockDim.x + threadIdx.x;
    if (i < NEXP) { g_cnt[i] = 0; g_cursor[i] = 0; }
    float4* o4 = (float4*)out;
    int n4 = n >> 2;
    float4 z = make_float4(0.f, 0.f, 0.f, 0.f);
    for (int j = i; j < n4; j += gridDim.x * blockDim.x) o4[j] = z;
}

// x -> fp16
__global__ void convert_x_kernel(const float* __restrict__ x) {
    int tot = NTOK * DMODEL / 4;
    for (int i = blockIdx.x * blockDim.x + threadIdx.x; i < tot; i += gridDim.x * blockDim.x) {
        float4 v = ((const float4*)x)[i];
        __half2* ph = (__half2*)(g_xh + (size_t)i * 4);
        ph[0] = __halves2half2(__float2half_rn(v.x), __float2half_rn(v.y));
        ph[1] = __halves2half2(__float2half_rn(v.z), __float2half_rn(v.w));
    }
}

// Transpose-convert: w [E][K][N] fp32 -> oh [E][N][K] fp16.
// 64(k) x 32(n) tile: MLP=8 on loads, full-width half2 stores.
__device__ __forceinline__ void transconv_body(const float* __restrict__ w,
                                               __half* __restrict__ oh,
                                               int K, int N) {
    __shared__ float t[64][33];   // [k][n]
    int e = blockIdx.z;
    const float* we = w + (size_t)e * K * N;
    int n0 = blockIdx.x * 32, k0 = blockIdx.y * 64;
    int tx = threadIdx.x, ty = threadIdx.y;   // 32 x 8
#pragma unroll
    for (int i = ty; i < 64; i += 8)
        t[i][tx] = we[(size_t)(k0 + i) * N + n0 + tx];
    __syncthreads();
    size_t ob = (size_t)e * N * K;
#pragma unroll
    for (int i = ty; i < 32; i += 8) {
        // row n0+i: thread tx emits halfs (k0+2tx, k0+2tx+1) -> 128B/warp store
        __half2 v = __halves2half2(__float2half_rn(t[2 * tx][i]),
                                   __float2half_rn(t[2 * tx + 1][i]));
        *(__half2*)(oh + ob + (size_t)(n0 + i) * K + k0 + 2 * tx) = v;
    }
}
__global__ void transconv_w1_kernel(const float* __restrict__ w1) {
    transconv_body(w1, g_w1h, DMODEL, FFN);
}
__global__ void transconv_w2_kernel(const float* __restrict__ w2) {
    transconv_body(w2, g_w2h, FFN, DMODEL);
}

// ---------------------------------------------------------------------------
// Router / offsets / scatter (validated)
// ---------------------------------------------------------------------------
__global__ void router_kernel(const float* __restrict__ x,
                              const float* __restrict__ rw,
                              const float* __restrict__ rb) {
    int warp = (blockIdx.x * blockDim.x + threadIdx.x) >> 5;
    int lane = threadIdx.x & 31;
    if (warp >= NTOK) return;
    const float* xr = x + (size_t)warp * DMODEL;
    float acc[NEXP];
#pragma unroll
    for (int e = 0; e < NEXP; e++) acc[e] = 0.0f;
    for (int d = lane; d < DMODEL; d += 32) {
        float xv = xr[d];
#pragma unroll
        for (int e = 0; e < NEXP; e++) acc[e] += xv * rw[d * NEXP + e];
    }
#pragma unroll
    for (int e = 0; e < NEXP; e++) {
#pragma unroll
        for (int o = 16; o > 0; o >>= 1) acc[e] += __shfl_xor_sync(0xffffffffu, acc[e], o);
    }
    if (lane == 0) {
        float l[NEXP];
#pragma unroll
        for (int e = 0; e < NEXP; e++) l[e] = acc[e] + rb[e];
        int i0 = 0;
#pragma unroll
        for (int e = 1; e < NEXP; e++) if (l[e] > l[i0]) i0 = e;
        int i1 = -1;
#pragma unroll
        for (int e = 0; e < NEXP; e++) {
            if (e == i0) continue;
            if (i1 < 0 || l[e] > l[i1]) i1 = e;
        }
        float z  = expf(l[i1] - l[i0]);
        float w0 = 1.0f / (1.0f + z);
        float w1 = z * w0;
        g_pick_e[warp * 2 + 0] = i0;  g_pick_w[warp * 2 + 0] = w0;
        g_pick_e[warp * 2 + 1] = i1;  g_pick_w[warp * 2 + 1] = w1;
        atomicAdd(&g_cnt[i0], 1);
        atomicAdd(&g_cnt[i1], 1);
    }
}

__global__ void offsets_kernel() {
    int s = 0;
#pragma unroll
    for (int e = 0; e < NEXP; e++) { g_off[e] = s; s += g_cnt[e]; }
}

__global__ void scatter_kernel() {
    int t = blockIdx.x * blockDim.x + threadIdx.x;
    if (t >= NTOK) return;
#pragma unroll
    for (int k = 0; k < TOPK; k++) {
        int e   = g_pick_e[t * 2 + k];
        int pos = atomicAdd(&g_cursor[e], 1);
        int row = g_off[e] + pos;
        g_tok[row]  = t;
        g_gate[row] = g_pick_w[t * 2 + k];
    }
}

// ---------------------------------------------------------------------------
// GEMM1 compute core: 128x128 tile, 8 warps (4M x 2N), BK=64
// ---------------------------------------------------------------------------
__device__ __forceinline__ void gemm1_chunk_compute(
    uint32_t st, int warpM, int warpN, int lane, float acc[2][8][4]) {
    uint32_t sA = st, sB = st + ABYTES;
    int r16 = lane & 15;
    int c8  = (lane >> 4) * 8;
#pragma unroll
    for (int ks = 0; ks < 4; ks++) {
        int kb = ks * 16 + c8;
        uint32_t ah[2][4], bb[8][2];
#pragma unroll
        for (int mf = 0; mf < 2; mf++) {
            uint32_t off = ((warpM * 32 + mf * 16 + r16) * PAD + kb) * 2;
            LDSM4(ah[mf][0], ah[mf][1], ah[mf][2], ah[mf][3], sA + off);
        }
#pragma unroll
        for (int nq = 0; nq < 4; nq++) {
            uint32_t off = ((warpN * 64 + nq * 16 + r16) * PAD + kb) * 2;
            uint32_t r0, r1, r2, r3;
            LDSM4(r0, r1, r2, r3, sB + off);
            bb[2 * nq][0] = r0; bb[2 * nq][1] = r2;
            bb[2 * nq + 1][0] = r1; bb[2 * nq + 1][1] = r3;
        }
#pragma unroll
        for (int mf = 0; mf < 2; mf++)
#pragma unroll
            for (int nf = 0; nf < 8; nf++)
                MMA16816(acc[mf][nf], ah[mf], bb[nf][0], bb[nf][1]);
    }
}

// ---------------------------------------------------------------------------
// GEMM1: hidden = relu(x[tok] @ w1[e] + b1[e]); emit fp16
// ---------------------------------------------------------------------------
__global__ __launch_bounds__(256)
void gemm1_mma(const float* __restrict__ b1) {
    int e = blockIdx.z;
    int cnt = g_cnt[e];
    int tm = blockIdx.y;
    if (tm * TILE >= cnt) return;
    int tn = blockIdx.x;
    int base = g_off[e];

    extern __shared__ __align__(16) char dyn[];
    __shared__ int s_tok[TILE];
    int tid = threadIdx.x, wid = tid >> 5, lane = tid & 31;
    int warpM = wid & 3, warpN = wid >> 2;

    if (tid < TILE) {
        int m = tm * TILE + tid;
        if (m >= cnt) m = cnt - 1;
        s_tok[tid] = g_tok[base + m];
    }
    __syncthreads();

    uint32_t sb = smem_u32(dyn);
    const __half* Bhg = g_w1h + (size_t)e * FFN * DMODEL + (size_t)tn * TILE * DMODEL;

    auto load_chunk = [&](int ch, int s) {
        uint32_t st = sb + s * STAGE;
        int koff = ch * BK;
#pragma unroll
        for (int q = 0; q < 4; q++) {
            int u = tid + q * 256;
            int r = u >> 3, j = u & 7;
            uint32_t so = (r * PAD + j * 8) * 2;
            CPA16(st + so,          g_xh + (size_t)s_tok[r] * DMODEL + koff + j * 8);
            CPA16(st + ABYTES + so, Bhg + (size_t)r * DMODEL + koff + j * 8);
        }
    };

    float acc[2][8][4];
#pragma unroll
    for (int i = 0; i < 2; i++)
#pragma unroll
        for (int j = 0; j < 8; j++)
#pragma unroll
            for (int c = 0; c < 4; c++) acc[i][j][c] = 0.f;

    const int NCH = DMODEL / BK;   // 8
    load_chunk(0, 0); CP_COMMIT();
    load_chunk(1, 1); CP_COMMIT();
    for (int c = 0; c < NCH; c++) {
        if (c + 2 < NCH) load_chunk(c + 2, (c + 2) % NSTG);
        CP_COMMIT();
        CP_WAIT2();
        __syncthreads();
        gemm1_chunk_compute(sb + (c % NSTG) * STAGE, warpM, warpN, lane, acc);
        __syncthreads();
    }

    int group = lane >> 2, tid4 = lane & 3;
#pragma unroll
    for (int mf = 0; mf < 2; mf++) {
#pragma unroll
        for (int half = 0; half < 2; half++) {
            int m = tm * TILE + warpM * 32 + mf * 16 + group + half * 8;
            if (m < cnt) {
                size_t hrow = (size_t)(base + m) * FFN;
#pragma unroll
                for (int nf = 0; nf < 8; nf++) {
                    int col = tn * TILE + warpN * 64 + nf * 8 + tid4 * 2;
                    float v0 = fmaxf(acc[mf][nf][half * 2 + 0] + b1[e * FFN + col],     0.f);
                    float v1 = fmaxf(acc[mf][nf][half * 2 + 1] + b1[e * FFN + col + 1], 0.f);
                    *(__half2*)(g_hh + hrow + col) =
                        __halves2half2(__float2half_rn(v0), __float2half_rn(v1));
                }
            }
        }
    }
}

// ---------------------------------------------------------------------------
// GEMM2: out += gate * (hidden @ w2[e] + b2[e]).
// TILE_M=64 (tail/quantization fix), TILE_N=128, 8 warps as 2M x 4N (32x32).
// ---------------------------------------------------------------------------
__device__ __forceinline__ void gemm2_chunk_compute(
    uint32_t st, int warpM, int warpN, int lane, float acc[2][4][4]) {
    uint32_t sA = st, sB = st + A2BYTES;
    int r16 = lane & 15;
    int c8  = (lane >> 4) * 8;
#pragma unroll
    for (int ks = 0; ks < 4; ks++) {
        int kb = ks * 16 + c8;
        uint32_t ah[2][4], bb[4][2];
#pragma unroll
        for (int mf = 0; mf < 2; mf++) {
            uint32_t off = ((warpM * 32 + mf * 16 + r16) * PAD + kb) * 2;
            LDSM4(ah[mf][0], ah[mf][1], ah[mf][2], ah[mf][3], sA + off);
        }
#pragma unroll
        for (int nq = 0; nq < 2; nq++) {
            uint32_t off = ((warpN * 32 + nq * 16 + r16) * PAD + kb) * 2;
            uint32_t r0, r1, r2, r3;
            LDSM4(r0, r1, r2, r3, sB + off);
            bb[2 * nq][0] = r0; bb[2 * nq][1] = r2;
            bb[2 * nq + 1][0] = r1; bb[2 * nq + 1][1] = r3;
        }
#pragma unroll
        for (int mf = 0; mf < 2; mf++)
#pragma unroll
            for (int nf = 0; nf < 4; nf++)
                MMA16816(acc[mf][nf], ah[mf], bb[nf][0], bb[nf][1]);
    }
}

__global__ __launch_bounds__(256)
void gemm2_mma(const float* __restrict__ b2, float* __restrict__ out) {
    int e = blockIdx.z;
    int cnt = g_cnt[e];
    int tm = blockIdx.y;
    if (tm * 64 >= cnt) return;
    int tn = blockIdx.x;
    int base = g_off[e];

    extern __shared__ __align__(16) char dyn[];
    __shared__ int s_row[64];
    int tid = threadIdx.x, wid = tid >> 5, lane = tid & 31;
    int warpM = wid & 1, warpN = wid >> 1;

    if (tid < 64) {
        int m = tm * 64 + tid;
        if (m >= cnt) m = cnt - 1;
        s_row[tid] = base + m;
    }
    __syncthreads();

    uint32_t sb = smem_u32(dyn);
    const __half* Bhg = g_w2h + (size_t)e * DMODEL * FFN + (size_t)tn * TILE * FFN;

    auto load_chunk = [&](int ch, int s) {
        uint32_t st = sb + s * STAGE2;
        int koff = ch * BK;
        // A: 64 rows x 8 units = 512 slots (2 passes)
#pragma unroll
        for (int q = 0; q < 2; q++) {
            int u = tid + q * 256;
            int r = u >> 3, j = u & 7;
            uint32_t so = (r * PAD + j * 8) * 2;
            CPA16(st + so, g_hh + (size_t)s_row[r] * FFN + koff + j * 8);
        }
        // B: 128 rows x 8 units = 1024 slots (4 passes)
#pragma unroll
        for (int q = 0; q < 4; q++) {
            int u = tid + q * 256;
            int r = u >> 3, j = u & 7;
            uint32_t so = (r * PAD + j * 8) * 2;
            CPA16(st + A2BYTES + so, Bhg + (size_t)r * FFN + koff + j * 8);
        }
    };

    float acc[2][4][4];
#pragma unroll
    for (int i = 0; i < 2; i++)
#pragma unroll
        for (int j = 0; j < 4; j++)
#pragma unroll
            for (int c = 0; c < 4; c++) acc[i][j][c] = 0.f;

    const int NCH = FFN / BK;   // 32
    load_chunk(0, 0); CP_COMMIT();
    load_chunk(1, 1); CP_COMMIT();
    for (int c = 0; c < NCH; c++) {
        if (c + 2 < NCH) load_chunk(c + 2, (c + 2) % NSTG);
        CP_COMMIT();
        CP_WAIT2();
        __syncthreads();
        gemm2_chunk_compute(sb + (c % NSTG) * STAGE2, warpM, warpN, lane, acc);
        __syncthreads();
    }

    int group = lane >> 2, tid4 = lane & 3;
#pragma unroll
    for (int mf = 0; mf < 2; mf++) {
#pragma unroll
        for (int half = 0; half < 2; half++) {
            int m = tm * 64 + warpM * 32 + mf * 16 + group + half * 8;
            if (m < cnt) {
                int   token = g_tok[base + m];
                float gate  = g_gate[base + m];
                float* orow = out + (size_t)token * DMODEL;
#pragma unroll
                for (int nf = 0; nf < 4; nf++) {
                    int col = tn * TILE + warpN * 32 + nf * 8 + tid4 * 2;
                    float v0 = (acc[mf][nf][half * 2 + 0] + b2[e * DMODEL + col])     * gate;
                    float v1 = (acc[mf][nf][half * 2 + 1] + b2[e * DMODEL + col + 1]) * gate;
                    atomicAdd(&orow[col],     v0);
                    atomicAdd(&orow[col + 1], v1);
                }
            }
        }
    }
}

// ---------------------------------------------------------------------------
extern "C" void kernel_launch(void* const* d_in, const int* in_sizes, int n_in,
                              void* d_out, int out_size) {
    const float* x   = (const float*)d_in[0];
    const float* rw  = (const float*)d_in[1];
    const float* rb  = (const float*)d_in[2];
    const float* w1  = (const float*)d_in[3];
    const float* b1  = (const float*)d_in[4];
    const float* w2  = (const float*)d_in[5];
    const float* b2  = (const float*)d_in[6];
    float* out = (float*)d_out;

    static bool attr_set = false;
    if (!attr_set) {
        cudaFuncSetAttribute(gemm1_mma, cudaFuncAttributeMaxDynamicSharedMemorySize, DSMEM1);
        cudaFuncSetAttribute(gemm2_mma, cudaFuncAttributeMaxDynamicSharedMemorySize, DSMEM2);
        attr_set = true;
    }

    zero_kernel<<<1024, 256>>>(out, NTOK * DMODEL);
    convert_x_kernel<<<1024, 256>>>(x);
    transconv_w1_kernel<<<dim3(FFN / 32, DMODEL / 64, NEXP), dim3(32, 8)>>>(w1);
    transconv_w2_kernel<<<dim3(DMODEL / 32, FFN / 64, NEXP), dim3(32, 8)>>>(w2);

    router_kernel<<<(NTOK * 32) / 256, 256>>>(x, rw, rb);
    offsets_kernel<<<1, 1>>>();
    scatter_kernel<<<NTOK / 256, 256>>>();

    gemm1_mma<<<dim3(FFN / TILE, NTOK / TILE, NEXP), 256, DSMEM1>>>(b1);
    gemm2_mma<<<dim3(DMODEL / TILE, NTOK / 64, NEXP), 256, DSMEM2>>>(b2, out);
}